// round 11
// baseline (speedup 1.0000x reference)
#include <cuda_runtime.h>
#include <math.h>

#define MAXL 12288
#define SPLITS 64
#define ROWS_PER_SPLIT 192          // MAXL / SPLITS
#define WORDS 24                    // ROWS_PER_SPLIT / 8
#define K1_THREADS 128
#define K2_THREADS 256
#define MAXBLK 256

// scratch: partial sums per row-split: [split][b(0..7)=acc, 8=count][column]
__device__ float g_part[SPLITS][9][MAXL];
// per-block partial squared-diff sums from k2
__device__ float g_bsum[MAXBLK][8];
// transposed predicts: [L][8]
__device__ float g_pt[MAXL * 8];
// mask bitmap: one 32-bit word per (split, 8-row word, float4-column)
// bit (u*4+c) = mask[i0 + w*8 + u][j4*4 + c] != 0
__device__ unsigned g_bits[SPLITS][WORDS][MAXL / 4];

__device__ __forceinline__ unsigned f2u(float x) { return __float_as_uint(x); }

// ---------------------------------------------------------------------------
// k0: transpose predicts [8][L] -> [L][8]
// ---------------------------------------------------------------------------
__global__ void k0_transpose(const float* __restrict__ predicts, int L)
{
    int i = blockIdx.x * 256 + threadIdx.x;
    if (i < L) {
        #pragma unroll
        for (int b = 0; b < 8; b++)
            g_pt[i * 8 + b] = predicts[b * L + i];
    }
}

// ---------------------------------------------------------------------------
// k1a: pure mask streaming. Double-buffered batches of 8 x LDG.128, compress
// to a 32-bit bitmap per (thread, 8 rows), popcount per component for counts.
// No dependent memory work -> should run at streaming bandwidth.
// Count semantics identical to the proven kernels: +1 per nonzero entry.
// ---------------------------------------------------------------------------
__global__ void k1a_maskscan(const float4* __restrict__ mask4, int L)
{
    const int L4 = L >> 2;
    const int j4 = blockIdx.x * K1_THREADS + threadIdx.x;   // grid exact
    const int s  = blockIdx.y;
    const int i0 = s * ROWS_PER_SPLIT;
    const float4* mcol = mask4 + j4;

    int c0 = 0, c1 = 0, c2 = 0, c3 = 0;

    float4 mb[2][8];
    #pragma unroll
    for (int u = 0; u < 8; u++)
        mb[0][u] = __ldg(mcol + (long long)(i0 + u) * L4);

    for (int w = 0; w < WORDS; w++) {
        const int cur = w & 1, nxt = cur ^ 1;
        if (w + 1 < WORDS) {
            #pragma unroll
            for (int u = 0; u < 8; u++)
                mb[nxt][u] = __ldg(mcol + (long long)(i0 + (w + 1) * 8 + u) * L4);
        }
        unsigned bits = 0;
        #pragma unroll
        for (int u = 0; u < 8; u++) {
            if (f2u(mb[cur][u].x)) bits |= 1u << (u * 4 + 0);
            if (f2u(mb[cur][u].y)) bits |= 1u << (u * 4 + 1);
            if (f2u(mb[cur][u].z)) bits |= 1u << (u * 4 + 2);
            if (f2u(mb[cur][u].w)) bits |= 1u << (u * 4 + 3);
        }
        g_bits[s][w][j4] = bits;
        c0 += __popc(bits & 0x11111111u);
        c1 += __popc(bits & 0x22222222u);
        c2 += __popc(bits & 0x44444444u);
        c3 += __popc(bits & 0x88888888u);
    }

    float4 cf = make_float4((float)c0, (float)c1, (float)c2, (float)c3);
    reinterpret_cast<float4*>(&g_part[s][8][0])[j4] = cf;
}

// ---------------------------------------------------------------------------
// k1b: sparse gather. Reads the 19 MB bitmap (instead of the 604 MB mask),
// gathers only active adj rows, FMAs against smem-staged predicts.
// Per-thread accumulation order identical to the proven fused kernels.
// ---------------------------------------------------------------------------
__global__ void k1b_gather(const float4* __restrict__ adj4, int L)
{
    __shared__ float4 sm_pt[ROWS_PER_SPLIT][2];             // 6 KB

    const int L4 = L >> 2;
    const int j4 = blockIdx.x * K1_THREADS + threadIdx.x;   // grid exact
    const int s  = blockIdx.y;
    const int i0 = s * ROWS_PER_SPLIT;
    const float4* acol = adj4 + j4;
    const float4* ptg  = reinterpret_cast<const float4*>(g_pt) + i0 * 2;

    for (int c = threadIdx.x; c < ROWS_PER_SPLIT * 2; c += K1_THREADS)
        (&sm_pt[0][0])[c] = __ldg(ptg + c);
    __syncthreads();

    float4 acc[8];
    #pragma unroll
    for (int b = 0; b < 8; b++) acc[b] = make_float4(0.f, 0.f, 0.f, 0.f);

    unsigned bits_cur = g_bits[s][0][j4];
    for (int w = 0; w < WORDS; w++) {
        unsigned bits_nxt = (w + 1 < WORDS) ? g_bits[s][w + 1][j4] : 0u;

        if (bits_cur) {
            #pragma unroll
            for (int u = 0; u < 8; u++) {
                unsigned rm = (bits_cur >> (u * 4)) & 0xFu;
                if (rm) {
                    int r = w * 8 + u;
                    float4 a  = __ldg(acol + (long long)(i0 + r) * L4);
                    float4 pA = sm_pt[r][0];
                    float4 pB = sm_pt[r][1];
                    float pb[8] = {pA.x, pA.y, pA.z, pA.w,
                                   pB.x, pB.y, pB.z, pB.w};

                    if (rm & 1u) {
                        #pragma unroll
                        for (int b = 0; b < 8; b++) acc[b].x = fmaf(pb[b], a.x, acc[b].x);
                    }
                    if (rm & 2u) {
                        #pragma unroll
                        for (int b = 0; b < 8; b++) acc[b].y = fmaf(pb[b], a.y, acc[b].y);
                    }
                    if (rm & 4u) {
                        #pragma unroll
                        for (int b = 0; b < 8; b++) acc[b].z = fmaf(pb[b], a.z, acc[b].z);
                    }
                    if (rm & 8u) {
                        #pragma unroll
                        for (int b = 0; b < 8; b++) acc[b].w = fmaf(pb[b], a.w, acc[b].w);
                    }
                }
            }
        }
        bits_cur = bits_nxt;
    }

    #pragma unroll
    for (int b = 0; b < 8; b++)
        reinterpret_cast<float4*>(&g_part[s][b][0])[j4] = acc[b];
}

// ---------------------------------------------------------------------------
// k2: per-column epilogue (unchanged, proven).
// ---------------------------------------------------------------------------
__global__ void __launch_bounds__(K2_THREADS)
k2_epilogue(const float* __restrict__ predicts,
            const float* __restrict__ sim,
            const float* __restrict__ mask,
            int L)
{
    __shared__ float s_sim[64];
    __shared__ float s_red[K2_THREADS / 32][8];

    int tid = threadIdx.x;
    if (tid < 64) s_sim[tid] = sim[tid];
    __syncthreads();

    int j = blockIdx.x * K2_THREADS + tid;
    float sq[8];
    #pragma unroll
    for (int b = 0; b < 8; b++) sq[b] = 0.f;

    if (j < L) {
        float acc[9];
        #pragma unroll
        for (int b = 0; b < 9; b++) acc[b] = 0.f;
        for (int s = 0; s < SPLITS; s++) {
            #pragma unroll
            for (int b = 0; b < 9; b++) acc[b] += g_part[s][b][j];
        }
        float mjj   = mask[(long long)j * L + j];
        float extra = 1.f - mjj;
        float inv_c = 1.f / (acc[8] + extra);

        float p[8], cand[8];
        #pragma unroll
        for (int b = 0; b < 8; b++) {
            p[b]    = predicts[b * L + j];
            cand[b] = (acc[b] + p[b] * extra) * inv_c;
        }
        #pragma unroll
        for (int b = 0; b < 8; b++) {
            float d = p[b];
            #pragma unroll
            for (int bb = 0; bb < 8; bb++)
                d = fmaf(-s_sim[b * 8 + bb], cand[bb], d);
            sq[b] = d * d;
        }
    }

    int lane = tid & 31, warp = tid >> 5;
    #pragma unroll
    for (int b = 0; b < 8; b++) {
        float v = sq[b];
        #pragma unroll
        for (int off = 16; off > 0; off >>= 1)
            v += __shfl_xor_sync(0xFFFFFFFFu, v, off);
        if (lane == 0) s_red[warp][b] = v;
    }
    __syncthreads();
    if (warp == 0) {
        #pragma unroll
        for (int b = 0; b < 8; b++) {
            float v = (lane < K2_THREADS / 32) ? s_red[lane][b] : 0.f;
            #pragma unroll
            for (int off = 4; off > 0; off >>= 1)
                v += __shfl_xor_sync(0xFFFFFFFFu, v, off);
            if (lane == 0) g_bsum[blockIdx.x][b] = v;
        }
    }
}

// ---------------------------------------------------------------------------
// k3: final scalar, parallelized (unchanged, proven).
// ---------------------------------------------------------------------------
__global__ void k3_final(const float* __restrict__ sim,
                         float* __restrict__ out,
                         int nblocks)
{
    __shared__ float s_ss[8], s_rs[8];
    int warp = threadIdx.x >> 5, lane = threadIdx.x & 31;

    if (warp < 8) {
        float v = 0.f;
        for (int k = lane; k < nblocks; k += 32) v += g_bsum[k][warp];
        #pragma unroll
        for (int off = 16; off > 0; off >>= 1)
            v += __shfl_xor_sync(0xFFFFFFFFu, v, off);

        float r = (lane < 8) ? sim[warp * 8 + lane] : 0.f;
        #pragma unroll
        for (int off = 4; off > 0; off >>= 1)
            r += __shfl_xor_sync(0xFFFFFFFFu, r, off);

        if (lane == 0) { s_ss[warp] = v; s_rs[warp] = r; }
    }
    __syncthreads();
    if (threadIdx.x == 0) {
        float total = 0.f, cnt = 0.f;
        #pragma unroll
        for (int b = 0; b < 8; b++) {
            if (s_rs[b] != 0.f) {
                total += sqrtf(s_ss[b]);
                cnt   += 1.f;
            }
        }
        out[0] = (cnt == 0.f) ? 0.f : total / fmaxf(cnt, 1.f);
    }
}

// ---------------------------------------------------------------------------
extern "C" void kernel_launch(void* const* d_in, const int* in_sizes, int n_in,
                              void* d_out, int out_size)
{
    const float* predicts = (const float*)d_in[0];
    const float* sim      = (const float*)d_in[1];
    const float* adj      = (const float*)d_in[2];
    const float* mask     = (const float*)d_in[3];
    float*       out      = (float*)d_out;

    const int B = 8;
    const int L = in_sizes[0] / B;        // 12288

    k0_transpose<<<(L + 255) / 256, 256>>>(predicts, L);

    int colblocks = (L / 4) / K1_THREADS;                      // 24, exact
    dim3 g1(colblocks, SPLITS);                                // 24 x 64 = 1536
    k1a_maskscan<<<g1, K1_THREADS>>>((const float4*)mask, L);
    k1b_gather<<<g1, K1_THREADS>>>((const float4*)adj, L);

    int k2blocks = (L + K2_THREADS - 1) / K2_THREADS;          // 48
    k2_epilogue<<<k2blocks, K2_THREADS>>>(predicts, sim, mask, L);

    k3_final<<<1, 256>>>(sim, out, k2blocks);
}

// round 12
// speedup vs baseline: 2.1020x; 2.1020x over previous
#include <cuda_runtime.h>
#include <math.h>

#define MAXL 12288
#define SPLITS 64
#define ROWS_PER_SPLIT 192          // MAXL / SPLITS, divisible by 4
#define K1_THREADS 128
#define K2_THREADS 256
#define MAXBLK 256

// scratch: partial sums per row-split: [split][b(0..7)=acc, 8=count][column]
__device__ float g_part[SPLITS][9][MAXL];
// reduced sums: [b(0..7)=acc, 8=count][column]
__device__ float g_sum[9][MAXL];
// per-block partial squared-diff sums from k2b
__device__ float g_bsum[MAXBLK][8];
// transposed predicts: [L][8]
__device__ float g_pt[MAXL * 8];

__device__ __forceinline__ unsigned f2u(float x) { return __float_as_uint(x); }

// ---------------------------------------------------------------------------
// k0: transpose predicts [8][L] -> [L][8]
// ---------------------------------------------------------------------------
__global__ void k0_transpose(const float* __restrict__ predicts, int L)
{
    int i = blockIdx.x * 256 + threadIdx.x;
    if (i < L) {
        #pragma unroll
        for (int b = 0; b < 8; b++)
            g_pt[i * 8 + b] = predicts[b * L + i];
    }
}

// ---------------------------------------------------------------------------
// k1: DENSE dual-stream masked accumulation. One thread = 4 columns (float4).
// mask AND adj are both read unconditionally (dense streaming: every DRAM
// page activation pulls full lines instead of ~32B, avoiding the
// activation-bound sparse-gather floor). Arithmetic is gated by m != 0 via
// branches/selects -- bit-identical to the proven R6-R9 semantics
// (select gives am = a or 0.0f; fmaf(p, 0, acc) == acc; cnt += 1 or 0).
// Double-buffered batches of 4 rows (mask+adj prefetched one iter ahead).
// ---------------------------------------------------------------------------
__global__ void k1_dense(const float4* __restrict__ adj4,
                         const float4* __restrict__ mask4,
                         int L)
{
    __shared__ float4 sm_pt[ROWS_PER_SPLIT][2];             // 6 KB

    const int L4 = L >> 2;
    const int j4 = blockIdx.x * K1_THREADS + threadIdx.x;   // grid exact
    const int s  = blockIdx.y;
    const int i0 = s * ROWS_PER_SPLIT;

    // stage predicts slice
    const float4* ptg = reinterpret_cast<const float4*>(g_pt) + i0 * 2;
    for (int c = threadIdx.x; c < ROWS_PER_SPLIT * 2; c += K1_THREADS)
        (&sm_pt[0][0])[c] = __ldg(ptg + c);
    __syncthreads();

    const float4* mcol = mask4 + j4;
    const float4* acol = adj4  + j4;

    float4 acc[8];
    #pragma unroll
    for (int b = 0; b < 8; b++) acc[b] = make_float4(0.f, 0.f, 0.f, 0.f);
    float4 cnt = make_float4(0.f, 0.f, 0.f, 0.f);

    // prologue: first batch of 4 rows (mask + adj, 8 independent LDG.128)
    float4 m_cur[4], a_cur[4];
    #pragma unroll
    for (int u = 0; u < 4; u++) {
        m_cur[u] = __ldg(mcol + (long long)(i0 + u) * L4);
        a_cur[u] = __ldg(acol + (long long)(i0 + u) * L4);
    }

    const int NIT = ROWS_PER_SPLIT / 4;     // 48
    for (int it = 0; it < NIT; it++) {
        float4 m_nxt[4], a_nxt[4];
        if (it + 1 < NIT) {
            const int ib = i0 + (it + 1) * 4;
            #pragma unroll
            for (int u = 0; u < 4; u++) {
                m_nxt[u] = __ldg(mcol + (long long)(ib + u) * L4);
                a_nxt[u] = __ldg(acol + (long long)(ib + u) * L4);
            }
        }

        // arithmetic skip only (loads already issued; adding zeros == skip)
        unsigned any = 0;
        #pragma unroll
        for (int u = 0; u < 4; u++)
            any |= f2u(m_cur[u].x) | f2u(m_cur[u].y) |
                   f2u(m_cur[u].z) | f2u(m_cur[u].w);

        if (any) {
            const int r = it * 4;
            #pragma unroll
            for (int u = 0; u < 4; u++) {
                unsigned ru = f2u(m_cur[u].x) | f2u(m_cur[u].y) |
                              f2u(m_cur[u].z) | f2u(m_cur[u].w);
                if (ru) {
                    float4 pA = sm_pt[r + u][0];
                    float4 pB = sm_pt[r + u][1];
                    float pb[8] = {pA.x, pA.y, pA.z, pA.w,
                                   pB.x, pB.y, pB.z, pB.w};

                    bool ox = f2u(m_cur[u].x) != 0u;
                    bool oy = f2u(m_cur[u].y) != 0u;
                    bool oz = f2u(m_cur[u].z) != 0u;
                    bool ow = f2u(m_cur[u].w) != 0u;
                    float amx = ox ? a_cur[u].x : 0.f;
                    float amy = oy ? a_cur[u].y : 0.f;
                    float amz = oz ? a_cur[u].z : 0.f;
                    float amw = ow ? a_cur[u].w : 0.f;
                    cnt.x += ox ? 1.f : 0.f;
                    cnt.y += oy ? 1.f : 0.f;
                    cnt.z += oz ? 1.f : 0.f;
                    cnt.w += ow ? 1.f : 0.f;

                    #pragma unroll
                    for (int b = 0; b < 8; b++) {
                        acc[b].x = fmaf(pb[b], amx, acc[b].x);
                        acc[b].y = fmaf(pb[b], amy, acc[b].y);
                        acc[b].z = fmaf(pb[b], amz, acc[b].z);
                        acc[b].w = fmaf(pb[b], amw, acc[b].w);
                    }
                }
            }
        }

        if (it + 1 < NIT) {
            #pragma unroll
            for (int u = 0; u < 4; u++) {
                m_cur[u] = m_nxt[u];
                a_cur[u] = a_nxt[u];
            }
        }
    }

    #pragma unroll
    for (int b = 0; b < 8; b++)
        reinterpret_cast<float4*>(&g_part[s][b][0])[j4] = acc[b];
    reinterpret_cast<float4*>(&g_part[s][8][0])[j4] = cnt;
}

// ---------------------------------------------------------------------------
// k2a: reduce g_part over splits -> g_sum. Grid (L/256, 9). Same sequential
// s-order as the proven single-kernel reduction (bit-identical sums).
// ---------------------------------------------------------------------------
__global__ void k2a_reduce(int L)
{
    int j = blockIdx.x * K2_THREADS + threadIdx.x;
    int b = blockIdx.y;
    if (j >= L) return;
    float v = 0.f;
    for (int s = 0; s < SPLITS; s++)
        v += g_part[s][b][j];
    g_sum[b][j] = v;
}

// ---------------------------------------------------------------------------
// k2b: per-column epilogue from g_sum (identical math to proven k2).
// ---------------------------------------------------------------------------
__global__ void __launch_bounds__(K2_THREADS)
k2b_epilogue(const float* __restrict__ predicts,
             const float* __restrict__ sim,
             const float* __restrict__ mask,
             int L)
{
    __shared__ float s_sim[64];
    __shared__ float s_red[K2_THREADS / 32][8];

    int tid = threadIdx.x;
    if (tid < 64) s_sim[tid] = sim[tid];
    __syncthreads();

    int j = blockIdx.x * K2_THREADS + tid;
    float sq[8];
    #pragma unroll
    for (int b = 0; b < 8; b++) sq[b] = 0.f;

    if (j < L) {
        float acc[9];
        #pragma unroll
        for (int b = 0; b < 9; b++) acc[b] = g_sum[b][j];

        float mjj   = mask[(long long)j * L + j];
        float extra = 1.f - mjj;
        float inv_c = 1.f / (acc[8] + extra);

        float p[8], cand[8];
        #pragma unroll
        for (int b = 0; b < 8; b++) {
            p[b]    = predicts[b * L + j];
            cand[b] = (acc[b] + p[b] * extra) * inv_c;
        }
        #pragma unroll
        for (int b = 0; b < 8; b++) {
            float d = p[b];
            #pragma unroll
            for (int bb = 0; bb < 8; bb++)
                d = fmaf(-s_sim[b * 8 + bb], cand[bb], d);
            sq[b] = d * d;
        }
    }

    int lane = tid & 31, warp = tid >> 5;
    #pragma unroll
    for (int b = 0; b < 8; b++) {
        float v = sq[b];
        #pragma unroll
        for (int off = 16; off > 0; off >>= 1)
            v += __shfl_xor_sync(0xFFFFFFFFu, v, off);
        if (lane == 0) s_red[warp][b] = v;
    }
    __syncthreads();
    if (warp == 0) {
        #pragma unroll
        for (int b = 0; b < 8; b++) {
            float v = (lane < K2_THREADS / 32) ? s_red[lane][b] : 0.f;
            #pragma unroll
            for (int off = 4; off > 0; off >>= 1)
                v += __shfl_xor_sync(0xFFFFFFFFu, v, off);
            if (lane == 0) g_bsum[blockIdx.x][b] = v;
        }
    }
}

// ---------------------------------------------------------------------------
// k3: final scalar, parallelized (unchanged, proven).
// ---------------------------------------------------------------------------
__global__ void k3_final(const float* __restrict__ sim,
                         float* __restrict__ out,
                         int nblocks)
{
    __shared__ float s_ss[8], s_rs[8];
    int warp = threadIdx.x >> 5, lane = threadIdx.x & 31;

    if (warp < 8) {
        float v = 0.f;
        for (int k = lane; k < nblocks; k += 32) v += g_bsum[k][warp];
        #pragma unroll
        for (int off = 16; off > 0; off >>= 1)
            v += __shfl_xor_sync(0xFFFFFFFFu, v, off);

        float r = (lane < 8) ? sim[warp * 8 + lane] : 0.f;
        #pragma unroll
        for (int off = 4; off > 0; off >>= 1)
            r += __shfl_xor_sync(0xFFFFFFFFu, r, off);

        if (lane == 0) { s_ss[warp] = v; s_rs[warp] = r; }
    }
    __syncthreads();
    if (threadIdx.x == 0) {
        float total = 0.f, cnt = 0.f;
        #pragma unroll
        for (int b = 0; b < 8; b++) {
            if (s_rs[b] != 0.f) {
                total += sqrtf(s_ss[b]);
                cnt   += 1.f;
            }
        }
        out[0] = (cnt == 0.f) ? 0.f : total / fmaxf(cnt, 1.f);
    }
}

// ---------------------------------------------------------------------------
extern "C" void kernel_launch(void* const* d_in, const int* in_sizes, int n_in,
                              void* d_out, int out_size)
{
    const float* predicts = (const float*)d_in[0];
    const float* sim      = (const float*)d_in[1];
    const float* adj      = (const float*)d_in[2];
    const float* mask     = (const float*)d_in[3];
    float*       out      = (float*)d_out;

    const int B = 8;
    const int L = in_sizes[0] / B;        // 12288

    k0_transpose<<<(L + 255) / 256, 256>>>(predicts, L);

    int colblocks = (L / 4) / K1_THREADS;                      // 24, exact
    dim3 g1(colblocks, SPLITS);                                // 24 x 64 = 1536
    k1_dense<<<g1, K1_THREADS>>>((const float4*)adj,
                                 (const float4*)mask, L);

    int jblocks = (L + K2_THREADS - 1) / K2_THREADS;           // 48
    dim3 g2a(jblocks, 9);
    k2a_reduce<<<g2a, K2_THREADS>>>(L);
    k2b_epilogue<<<jblocks, K2_THREADS>>>(predicts, sim, mask, L);

    k3_final<<<1, 256>>>(sim, out, jblocks);
}